// round 14
// baseline (speedup 1.0000x reference)
#include <cuda_runtime.h>

// Ragged segment mean: out[b,d] = mean(seq[b, begin[b]:end[b], d])
// B=2048, L=512, D=512, fp32.
//
// D-eighth split. R9 (D-quarter, 8192 CTAs) hit 86.5us @ 78.8%
// DRAM; residual loss is the end-of-kernel tail, which scales with max
// per-CTA work (was 256 rows x 512B = 128KB). Halve the quantum: grid
// (B, 8), each CTA reduces the full segment over a 256B D-slice ->
// max 64KB/CTA, 16384 CTAs, ~7 waves. Coalescing preserved: each
// half-warp reads 256 contiguous bytes; a warp covers 2 rows = 4 full
// 128B lines; the 8 sibling CTAs tile each 2KB row disjointly.

static constexpr int L_DIM  = 512;
static constexpr int D_VEC  = 512 / 4;    // 128 float4 per full row
static constexpr int S_VEC  = 16;         // 16 float4 per D-eighth (256B)
static constexpr int NTHR   = 128;        // 8 row-offsets x 16 slots

__global__ __launch_bounds__(NTHR) void ragged_mean_dsplit8(
    const float* __restrict__ seq,
    const int*   __restrict__ begin,
    const int*   __restrict__ end,
    float*       __restrict__ out)
{
    const int b = blockIdx.x;
    const int j = blockIdx.y;             // D-eighth 0..7
    const int t = threadIdx.x;
    const int r = t >> 4;                 // row offset 0..7
    const int c = t & 15;                 // float4 slot 0..15

    const int s = begin[b];
    const int e = end[b];

    const float4* __restrict__ base =
        reinterpret_cast<const float4*>(seq)
        + (size_t)b * L_DIM * D_VEC + (size_t)j * S_VEC + c;

    float ax = 0.f, ay = 0.f, az = 0.f, aw = 0.f;

    // row-offset group r handles rows s+r, s+r+8, s+r+16, ...
    int l = s + r;
    for (; l + 24 < e; l += 32) {
        float4 v0 = base[(size_t)(l +  0) * D_VEC];
        float4 v1 = base[(size_t)(l +  8) * D_VEC];
        float4 v2 = base[(size_t)(l + 16) * D_VEC];
        float4 v3 = base[(size_t)(l + 24) * D_VEC];
        ax += v0.x; ay += v0.y; az += v0.z; aw += v0.w;
        ax += v1.x; ay += v1.y; az += v1.z; aw += v1.w;
        ax += v2.x; ay += v2.y; az += v2.z; aw += v2.w;
        ax += v3.x; ay += v3.y; az += v3.z; aw += v3.w;
    }
    for (; l < e; l += 8) {
        float4 v = base[(size_t)l * D_VEC];
        ax += v.x; ay += v.y; az += v.z; aw += v.w;
    }

    // cross-group reduction: 8 partials per slot, fixed order -> deterministic
    __shared__ float4 red[8][S_VEC];
    red[r][c] = make_float4(ax, ay, az, aw);
    __syncthreads();

    if (r == 0) {
        float sx = 0.f, sy = 0.f, sz = 0.f, sw = 0.f;
        #pragma unroll
        for (int g = 0; g < 8; ++g) {
            float4 p = red[g][c];
            sx += p.x; sy += p.y; sz += p.z; sw += p.w;
        }
        const float inv = 1.0f / (float)(e - s);
        float4 o;
        o.x = sx * inv; o.y = sy * inv; o.z = sz * inv; o.w = sw * inv;
        reinterpret_cast<float4*>(out)[(size_t)b * D_VEC + j * S_VEC + c] = o;
    }
}

extern "C" void kernel_launch(void* const* d_in, const int* in_sizes, int n_in,
                              void* d_out, int out_size)
{
    const float* seq   = (const float*)d_in[0];
    const int*   begin = (const int*)d_in[1];
    const int*   end   = (const int*)d_in[2];
    float*       out   = (float*)d_out;

    const int B = in_sizes[1];   // 2048

    dim3 grid(B, 8);
    ragged_mean_dsplit8<<<grid, NTHR>>>(seq, begin, end, out);
}

// round 17
// speedup vs baseline: 1.0270x; 1.0270x over previous
#include <cuda_runtime.h>

// Ragged segment mean: out[b,d] = mean(seq[b, begin[b]:end[b], d])
// B=2048, L=512, D=512, fp32.
//
// R9's D-quarter split (best: 86.5us @ 78.8% DRAM) with grid dims
// SWAPPED to (4, B). Evidence: finer D-splits regressed (R14), pointing at
// DRAM page locality: with grid (B,4), x-fastest linearization launches all
// j=0 CTAs before any j=1, so only 512B of each 2KB row is read at a time
// and every DRAM page is activated 4x. With grid (4,B) the four sibling
// CTAs (b, 0..3) are launch-adjacent -> co-resident -> the full 2KB row is
// streamed concurrently; pages activate once, L2 sees dense streams.
// Work assignment per CTA is bit-identical to R9.

static constexpr int L_DIM  = 512;
static constexpr int D_VEC  = 512 / 4;    // 128 float4 per full row
static constexpr int Q_VEC  = 32;         // 32 float4 per D-quarter
static constexpr int NTHR   = 128;        // 4 warps: (row-offset, slot)

__global__ __launch_bounds__(NTHR) void ragged_mean_dsplit_sw(
    const float* __restrict__ seq,
    const int*   __restrict__ begin,
    const int*   __restrict__ end,
    float*       __restrict__ out)
{
    const int j = blockIdx.x;             // D-quarter 0..3  (fast index)
    const int b = blockIdx.y;             // batch           (slow index)
    const int t = threadIdx.x;
    const int r = t >> 5;                 // row offset within 4-row group, 0..3
    const int c = t & 31;                 // float4 slot within quarter, 0..31

    const int s = begin[b];
    const int e = end[b];

    const float4* __restrict__ base =
        reinterpret_cast<const float4*>(seq)
        + (size_t)b * L_DIM * D_VEC + (size_t)j * Q_VEC + c;

    float ax = 0.f, ay = 0.f, az = 0.f, aw = 0.f;

    // warp r handles rows s+r, s+r+4, s+r+8, ... (512 contiguous bytes per
    // warp-row = 4 full 128B lines)
    int l = s + r;
    for (; l + 12 < e; l += 16) {
        float4 v0 = base[(size_t)(l +  0) * D_VEC];
        float4 v1 = base[(size_t)(l +  4) * D_VEC];
        float4 v2 = base[(size_t)(l +  8) * D_VEC];
        float4 v3 = base[(size_t)(l + 12) * D_VEC];
        ax += v0.x; ay += v0.y; az += v0.z; aw += v0.w;
        ax += v1.x; ay += v1.y; az += v1.z; aw += v1.w;
        ax += v2.x; ay += v2.y; az += v2.z; aw += v2.w;
        ax += v3.x; ay += v3.y; az += v3.z; aw += v3.w;
    }
    for (; l < e; l += 4) {
        float4 v = base[(size_t)l * D_VEC];
        ax += v.x; ay += v.y; az += v.z; aw += v.w;
    }

    // cross-warp reduction: 4 partials per slot, fixed order -> deterministic
    __shared__ float4 red[4][Q_VEC];
    red[r][c] = make_float4(ax, ay, az, aw);
    __syncthreads();

    if (r == 0) {
        float4 p0 = red[0][c];
        float4 p1 = red[1][c];
        float4 p2 = red[2][c];
        float4 p3 = red[3][c];
        const float inv = 1.0f / (float)(e - s);
        float4 o;
        o.x = (p0.x + p1.x + p2.x + p3.x) * inv;
        o.y = (p0.y + p1.y + p2.y + p3.y) * inv;
        o.z = (p0.z + p1.z + p2.z + p3.z) * inv;
        o.w = (p0.w + p1.w + p2.w + p3.w) * inv;
        reinterpret_cast<float4*>(out)[(size_t)b * D_VEC + j * Q_VEC + c] = o;
    }
}

extern "C" void kernel_launch(void* const* d_in, const int* in_sizes, int n_in,
                              void* d_out, int out_size)
{
    const float* seq   = (const float*)d_in[0];
    const int*   begin = (const int*)d_in[1];
    const int*   end   = (const int*)d_in[2];
    float*       out   = (float*)d_out;

    const int B = in_sizes[1];   // 2048

    dim3 grid(4, B);             // j fast, b slow: siblings co-resident
    ragged_mean_dsplit_sw<<<grid, NTHR>>>(seq, begin, end, out);
}